// round 7
// baseline (speedup 1.0000x reference)
#include <cuda_runtime.h>
#include <cuda_fp16.h>
#include <cstdint>

#define NB 2
#define NN 512
#define NE 128
#define NH 256

// A tile: 128 rows x 296 halves (592 B stride; (r*148)%32 distinct -> conflict-free)
#define STRA_B 592
// B chunk buffer: 256 n-rows x 48 k halves, padded to 112 B rows ((r*28)%32 distinct)
#define STRB_B 112
#define BBUF_B 28672
#define OFF_A   0
#define OFF_B   75776
#define OFF_P   161792
#define OFF_W3  162816
#define OFF_NI  163840
#define OFF_RED 164352
#define SMEM_REQ 166400

#define KPAD1 144
#define KPAD2 272

// device scratch (allocation-free rule)
__device__ float g_P[NB * NN * NH];      // hi @ W1[0:128]   exact fp32
__device__ float g_Q[NB * NN * NH];      // hj @ W1[128:256] exact fp32
__device__ float g_raw[NB * NN * NN];
__device__ __half g_B1h[256 * KPAD1];    // L1 B: [n][k] fp16 (k: habs128, d, 1, pad)
__device__ __half g_B2h[256 * KPAD2];    // L2 B: [n][k] fp16 (k: 256, b2, pad)

// ---------------- PTX helpers ----------------
__device__ __forceinline__ uint32_t smem_u32(const void* p) {
    uint32_t a;
    asm("{ .reg .u64 t; cvta.to.shared.u64 t, %1; cvt.u32.u64 %0, t; }" : "=r"(a) : "l"(p));
    return a;
}
#define LDSM4(R, A) \
    asm volatile("ldmatrix.sync.aligned.m8n8.x4.shared.b16 {%0,%1,%2,%3}, [%4];" \
        : "=r"((R)[0]), "=r"((R)[1]), "=r"((R)[2]), "=r"((R)[3]) : "r"(A))
#define LDSM2(R, A) \
    asm volatile("ldmatrix.sync.aligned.m8n8.x2.shared.b16 {%0,%1}, [%2];" \
        : "=r"((R)[0]), "=r"((R)[1]) : "r"(A))
#define MMA_F16(C, Ar, Br) \
    asm volatile("mma.sync.aligned.m16n8k16.row.col.f32.f16.f16.f32 " \
        "{%0,%1,%2,%3}, {%4,%5,%6,%7}, {%8,%9}, {%0,%1,%2,%3};" \
        : "+f"((C)[0]), "+f"((C)[1]), "+f"((C)[2]), "+f"((C)[3]) \
        : "r"((Ar)[0]), "r"((Ar)[1]), "r"((Ar)[2]), "r"((Ar)[3]), \
          "r"((Br)[0]), "r"((Br)[1]))
#define CP16(d, s)  asm volatile("cp.async.ca.shared.global [%0], [%1], 16;" :: "r"(d), "l"(s))
#define CPCOMMIT()  asm volatile("cp.async.commit_group;" ::: "memory")
#define CPWAIT1()   asm volatile("cp.async.wait_group 1;" ::: "memory")
#define CPWAIT0()   asm volatile("cp.async.wait_group 0;" ::: "memory")

// ---------------- merged prep kernel ----------------
__global__ void prep_all(const float* __restrict__ node, const float* __restrict__ W1,
                         const float* __restrict__ b1, const float* __restrict__ W2,
                         const float* __restrict__ b2) {
    const int t = threadIdx.x;
    if (blockIdx.x < 1024) {
        // P, Q precompute
        const int row = blockIdx.x;
        __shared__ float ns[NE];
        if (t < NE) ns[t] = node[row * NE + t];
        __syncthreads();
        float p = 0.f, q = 0.f;
#pragma unroll 8
        for (int e = 0; e < NE; e++) {
            float nv = ns[e];
            p = fmaf(nv, W1[e * NH + t], p);
            q = fmaf(nv, W1[(NE + e) * NH + t], q);
        }
        g_P[row * NH + t] = p;
        g_Q[row * NH + t] = q;
    } else {
        int idx = (blockIdx.x - 1024) * 256 + t;
        if (idx < 256 * KPAD1) {
            int n = idx / KPAD1, k = idx % KPAD1;
            float v = (k < 128) ? W1[(256 + k) * NH + n]
                    : (k == 128) ? W1[384 * NH + n]
                    : (k == 129) ? b1[n] : 0.f;
            g_B1h[idx] = __float2half_rn(v);
        } else {
            int i2 = idx - 256 * KPAD1;
            if (i2 < 256 * KPAD2) {
                int n = i2 / KPAD2, k = i2 % KPAD2;
                float v = (k < 256) ? W2[k * NH + n]
                        : (k == 256) ? b2[n] : 0.f;
                g_B2h[i2] = __float2half_rn(v);
            }
        }
    }
}

// ---------------- main fused kernel ----------------
__global__ void __launch_bounds__(256, 1)
edge_mlp_mma(const float* __restrict__ node, const float* __restrict__ euclid,
             const float* __restrict__ W3, const float* __restrict__ b3) {
    extern __shared__ char smc[];
    __half* smA  = (__half*)(smc + OFF_A);
    float* P_s   = (float*)(smc + OFF_P);
    float* w3_s  = (float*)(smc + OFF_W3);
    float* ni_s  = (float*)(smc + OFF_NI);
    float* red_s = (float*)(smc + OFF_RED);
    const uint32_t sb = smem_u32(smc);

    const int tid = threadIdx.x, L = tid & 31, wid = tid >> 5;
    const int mw = wid >> 2, nw = wid & 3;           // 2 x 4 warp grid, tile 64x64
    const int m0 = mw * 64, n0 = nw * 64;
    const int b = blockIdx.z, i = blockIdx.y, j0 = blockIdx.x << 7;

    // chunk table: c 0..2 = L1, c 3..8 = L2 (c==8 is 32-k wide)
    auto chunk_src = [&](int c) -> const __half* {
        return (c < 3) ? (g_B1h + (size_t)tid * KPAD1 + c * 48)
                       : (g_B2h + (size_t)tid * KPAD2 + (c - 3) * 48);
    };
    auto issue_chunk = [&](int c) {
        const __half* src = chunk_src(c);
        uint32_t dst = sb + OFF_B + (uint32_t)(c % 3) * BBUF_B + (uint32_t)tid * STRB_B;
        int ns = (c == 8) ? 4 : 6;
#pragma unroll
        for (int s = 0; s < 6; s++)
            if (s < ns) CP16(dst + s * 16, src + s * 8);
        CPCOMMIT();
    };

    // prologue: prefetch chunks 0,1 (overlaps A staging)
    issue_chunk(0);
    issue_chunk(1);

    // stage small vectors
    P_s[tid]  = g_P[(b * NN + i) * NH + tid];
    w3_s[tid] = W3[tid];
    if (tid < NE) ni_s[tid] = node[(size_t)(b * NN + i) * NE + tid];
    __syncthreads();

    // ---- stage A (L1): rows = 128 j-pairs, cols [habs(128) | d | 1 | pad(14)]
    {
        int row = tid >> 1, half = tid & 1;
        const float4* nj = (const float4*)(node + (size_t)(b * NN + j0 + row) * NE);
        __half* dst = (__half*)((char*)smA + row * STRA_B) + half * 64;
        const float* nip = ni_s + half * 64;
#pragma unroll 8
        for (int q = 0; q < 16; q++) {
            float4 v = nj[half * 16 + q];
            __half2 h0 = __floats2half2_rn(fabsf(nip[q * 4 + 0] - v.x),
                                           fabsf(nip[q * 4 + 1] - v.y));
            __half2 h1v = __floats2half2_rn(fabsf(nip[q * 4 + 2] - v.z),
                                            fabsf(nip[q * 4 + 3] - v.w));
            *(__half2*)(dst + q * 4)     = h0;
            *(__half2*)(dst + q * 4 + 2) = h1v;
        }
        if (tid < 128) {
            float d = euclid[(size_t)(b * NN + i) * NN + j0 + tid];
            __half* rr = (__half*)((char*)smA + tid * STRA_B);
            rr[128] = __float2half_rn(d);
            rr[129] = __float2half_rn(1.0f);
#pragma unroll
            for (int u = 65; u < 72; u++) ((uint32_t*)rr)[u] = 0u;  // halves 130..143
        }
    }

    float acc[4][8][4];
#pragma unroll
    for (int mt = 0; mt < 4; mt++)
#pragma unroll
        for (int nt = 0; nt < 8; nt++)
#pragma unroll
            for (int r = 0; r < 4; r++) acc[mt][nt][r] = 0.f;

    // per-thread ldmatrix bases
    const uint32_t rowA = (L & 7) + ((L >> 3) & 1) * 8;
    const uint32_t colA = (L >> 4) * 16;
    const uint32_t aBase = sb + OFF_A + (m0 + rowA) * STRA_B + colA;
    const uint32_t bOff = (n0 + (L & 7)) * STRB_B + ((L >> 3) & 1) * 16;

    // ---- unified 9-chunk pipeline: wait -> barrier -> issue(c+2) -> mma(c) ----
    for (int c = 0; c < 9; c++) {
        if (c < 8) CPWAIT1(); else CPWAIT0();
        __syncthreads();                 // chunk c visible to all; WAR-safe issue below
        if (c + 2 < 9) issue_chunk(c + 2);

        uint32_t bBase = sb + OFF_B + (uint32_t)(c % 3) * BBUF_B + bOff;
        uint32_t aK = aBase + (uint32_t)((c < 3 ? c : c - 3) * 96);
        int nks = (c == 8) ? 2 : 3;
        for (int ks = 0; ks < nks; ks++) {
            uint32_t a[4][4], bf[8][2];
            uint32_t aa = aK + ks * 32;
            uint32_t ba = bBase + ks * 32;
#pragma unroll
            for (int mt = 0; mt < 4; mt++) LDSM4(a[mt], aa + mt * 16 * STRA_B);
#pragma unroll
            for (int nt = 0; nt < 8; nt++) LDSM2(bf[nt], ba + nt * 8 * STRB_B);
#pragma unroll
            for (int mt = 0; mt < 4; mt++)
#pragma unroll
                for (int nt = 0; nt < 8; nt++) MMA_F16(acc[mt][nt], a[mt], bf[nt]);
        }

        if (c == 2) {
            // L1 done -> epilogue 1: h1 = relu(acc + P[i] + Q[j]) -> fp16 A tile
            __syncthreads();             // all warps finished reading A (L1 cols)
#pragma unroll
            for (int mt = 0; mt < 4; mt++) {
                int r0 = m0 + mt * 16 + (L >> 2);
                const float* qA = g_Q + ((size_t)(b * NN + j0 + r0)) * NH;
                const float* qB = qA + 8 * NH;
#pragma unroll
                for (int nt = 0; nt < 8; nt++) {
                    int cb = n0 + nt * 8 + (L & 3) * 2;
                    float p0 = P_s[cb], p1 = P_s[cb + 1];
                    float2 qa = *(const float2*)(qA + cb);
                    float2 qb = *(const float2*)(qB + cb);
                    __half2 v0 = __floats2half2_rn(fmaxf(acc[mt][nt][0] + p0 + qa.x, 0.f),
                                                   fmaxf(acc[mt][nt][1] + p1 + qa.y, 0.f));
                    __half2 v1 = __floats2half2_rn(fmaxf(acc[mt][nt][2] + p0 + qb.x, 0.f),
                                                   fmaxf(acc[mt][nt][3] + p1 + qb.y, 0.f));
                    *(__half2*)((char*)smA + r0 * STRA_B + cb * 2) = v0;
                    *(__half2*)((char*)smA + (r0 + 8) * STRA_B + cb * 2) = v1;
                    acc[mt][nt][0] = 0.f; acc[mt][nt][1] = 0.f;
                    acc[mt][nt][2] = 0.f; acc[mt][nt][3] = 0.f;
                }
            }
            if (tid < 128) {
                __half* rr = (__half*)((char*)smA + tid * STRA_B);
                *(__half2*)(rr + 256) = __floats2half2_rn(1.0f, 0.0f);  // bias col + pad
#pragma unroll
                for (int u = 129; u < 136; u++) ((uint32_t*)rr)[u] = 0u; // halves 258..271
            }
            // next loop iteration's barrier publishes the new A tile before mma(3)
        }
    }

    // ---- epilogue 2: out = relu(acc) . W3  (b2 folded via 1-column) ----
    float w3c[16];
#pragma unroll
    for (int nt = 0; nt < 8; nt++) {
        int cb = n0 + nt * 8 + (L & 3) * 2;
        w3c[nt * 2] = w3_s[cb];
        w3c[nt * 2 + 1] = w3_s[cb + 1];
    }
    float rs[8];
#pragma unroll
    for (int mt = 0; mt < 4; mt++) {
        float s0 = 0.f, s1 = 0.f;
#pragma unroll
        for (int nt = 0; nt < 8; nt++) {
            s0 = fmaf(fmaxf(acc[mt][nt][0], 0.f), w3c[nt * 2], s0);
            s0 = fmaf(fmaxf(acc[mt][nt][1], 0.f), w3c[nt * 2 + 1], s0);
            s1 = fmaf(fmaxf(acc[mt][nt][2], 0.f), w3c[nt * 2], s1);
            s1 = fmaf(fmaxf(acc[mt][nt][3], 0.f), w3c[nt * 2 + 1], s1);
        }
        rs[mt * 2] = s0;
        rs[mt * 2 + 1] = s1;
    }
#pragma unroll
    for (int r = 0; r < 8; r++) {
        float v = rs[r];
        v += __shfl_xor_sync(0xffffffffu, v, 1);
        v += __shfl_xor_sync(0xffffffffu, v, 2);
        if ((L & 3) == 0) {
            int m = m0 + (r >> 1) * 16 + (r & 1) * 8 + (L >> 2);
            red_s[m * 4 + nw] = v;
        }
    }
    __syncthreads();
    if (tid < 128) {
        float o = red_s[tid * 4] + red_s[tid * 4 + 1] +
                  red_s[tid * 4 + 2] + red_s[tid * 4 + 3] + b3[0];
        g_raw[(size_t)(b * NN + i) * NN + j0 + tid] = o;
    }
}

// ---------------- symmetrize + zero diagonal ----------------
__global__ void symmetrize(float* __restrict__ out) {
    int idx = blockIdx.x * 256 + threadIdx.x;
    int b = idx >> 18;
    int r = idx & 262143;
    int i = r >> 9;
    int j = r & 511;
    float v = 0.f;
    if (i != j)
        v = 0.5f * (g_raw[idx] + g_raw[(b << 18) + (j << 9) + i]);
    out[idx] = v;
}

extern "C" void kernel_launch(void* const* d_in, const int* in_sizes, int n_in,
                              void* d_out, int out_size) {
    const float* node   = (const float*)d_in[0];
    const float* euclid = (const float*)d_in[2];
    const float* W1 = (const float*)d_in[3];
    const float* b1 = (const float*)d_in[4];
    const float* W2 = (const float*)d_in[5];
    const float* b2 = (const float*)d_in[6];
    const float* W3 = (const float*)d_in[7];
    const float* b3 = (const float*)d_in[8];
    float* out = (float*)d_out;

    cudaFuncSetAttribute(edge_mlp_mma, cudaFuncAttributeMaxDynamicSharedMemorySize,
                         SMEM_REQ);

    prep_all<<<1024 + 416, 256>>>(node, W1, b1, W2, b2);
    dim3 grid(NN / 128, NN, NB);
    edge_mlp_mma<<<grid, 256, SMEM_REQ>>>(node, euclid, W3, b3);
    symmetrize<<<(NB * NN * NN) / 256, 256>>>(out);
}

// round 8
// speedup vs baseline: 1.3753x; 1.3753x over previous
#include <cuda_runtime.h>
#include <cuda_fp16.h>
#include <cstdint>

#define NB 2
#define NN 512
#define NE 128
#define NH 256

// A tile: 128 rows x 264 halves (528 B stride; 16r mod 128 distinct -> conflict-free)
#define STRA_B 528
// B chunk: 256 n-rows x 32 k halves, padded to 80 B rows (conflict-free)
#define STRB_B 80
#define BCHUNK_B 20480
#define OFF_A    0
#define OFF_B    67584
#define OFF_P    108544
#define OFF_W1E  109568
#define OFF_B2V  110592
#define OFF_W3   111616
#define OFF_NI   112640
#define OFF_D    113152
#define OFF_RED  113664
#define SMEM_REQ 115712

// device scratch (allocation-free rule)
__device__ float g_P[NB * NN * NH];      // hi @ W1[0:128] + b1   exact fp32
__device__ float g_Q[NB * NN * NH];      // hj @ W1[128:256]      exact fp32
__device__ float g_raw[NB * NN * NN];
__device__ __half g_B1h[4 * 256 * 32];   // L1 B: [chunk][n][k] fp16 = W1[256:384]^T
__device__ __half g_B2h[8 * 256 * 32];   // L2 B: [chunk][n][k] fp16 = W2^T

// ---------------- PTX helpers ----------------
__device__ __forceinline__ uint32_t smem_u32(const void* p) {
    uint32_t a;
    asm("{ .reg .u64 t; cvta.to.shared.u64 t, %1; cvt.u32.u64 %0, t; }" : "=r"(a) : "l"(p));
    return a;
}
#define LDSM4(R, A) \
    asm volatile("ldmatrix.sync.aligned.m8n8.x4.shared.b16 {%0,%1,%2,%3}, [%4];" \
        : "=r"((R)[0]), "=r"((R)[1]), "=r"((R)[2]), "=r"((R)[3]) : "r"(A))
#define LDSM2(R, A) \
    asm volatile("ldmatrix.sync.aligned.m8n8.x2.shared.b16 {%0,%1}, [%2];" \
        : "=r"((R)[0]), "=r"((R)[1]) : "r"(A))
#define MMA_F16(C, Ar, Br) \
    asm volatile("mma.sync.aligned.m16n8k16.row.col.f32.f16.f16.f32 " \
        "{%0,%1,%2,%3}, {%4,%5,%6,%7}, {%8,%9}, {%0,%1,%2,%3};" \
        : "+f"((C)[0]), "+f"((C)[1]), "+f"((C)[2]), "+f"((C)[3]) \
        : "r"((Ar)[0]), "r"((Ar)[1]), "r"((Ar)[2]), "r"((Ar)[3]), \
          "r"((Br)[0]), "r"((Br)[1]))
#define CP16(d, s)  asm volatile("cp.async.ca.shared.global [%0], [%1], 16;" :: "r"(d), "l"(s))
#define CPCOMMIT()  asm volatile("cp.async.commit_group;" ::: "memory")
#define CPWAIT1()   asm volatile("cp.async.wait_group 1;" ::: "memory")

// ---------------- merged prep kernel ----------------
__global__ void prep_all(const float* __restrict__ node, const float* __restrict__ W1,
                         const float* __restrict__ b1, const float* __restrict__ W2) {
    const int t = threadIdx.x;
    if (blockIdx.x < 1024) {
        const int row = blockIdx.x;
        __shared__ float ns[NE];
        if (t < NE) ns[t] = node[row * NE + t];
        __syncthreads();
        float p = 0.f, q = 0.f;
#pragma unroll 8
        for (int e = 0; e < NE; e++) {
            float nv = ns[e];
            p = fmaf(nv, W1[e * NH + t], p);
            q = fmaf(nv, W1[(NE + e) * NH + t], q);
        }
        g_P[row * NH + t] = p + b1[t];      // fold b1 into P
        g_Q[row * NH + t] = q;
    } else {
        int idx = (blockIdx.x - 1024) * 256 + t;   // 0 .. 98303
        if (idx < 4 * 8192) {
            int c = idx >> 13, n = (idx >> 5) & 255, kk = idx & 31;
            g_B1h[idx] = __float2half_rn(W1[(256 + c * 32 + kk) * NH + n]);
        } else {
            int i2 = idx - 4 * 8192;               // 0 .. 65535
            int c = i2 >> 13, n = (i2 >> 5) & 255, kk = i2 & 31;
            g_B2h[i2] = __float2half_rn(W2[(c * 32 + kk) * NH + n]);
        }
    }
}

// ---------------- GEMM inner: one 32-k chunk = 2 k16 steps (warp tile 64x64) ----
__device__ __forceinline__ void mma_chunk2(float (&acc)[4][8][4],
                                           uint32_t aK, uint32_t bB) {
#pragma unroll
    for (int ks = 0; ks < 2; ks++) {
        uint32_t a[4][4], bf[8][2];
        uint32_t aa = aK + ks * 32;       // +16 halves
        uint32_t ba = bB + ks * 32;
#pragma unroll
        for (int mt = 0; mt < 4; mt++) LDSM4(a[mt], aa + mt * 16 * STRA_B);
#pragma unroll
        for (int nt = 0; nt < 8; nt++) LDSM2(bf[nt], ba + nt * 8 * STRB_B);
#pragma unroll
        for (int mt = 0; mt < 4; mt++)
#pragma unroll
            for (int nt = 0; nt < 8; nt++) MMA_F16(acc[mt][nt], a[mt], bf[nt]);
    }
}

// ---------------- main fused kernel ----------------
__global__ void __launch_bounds__(256, 1)
edge_mlp_mma(const float* __restrict__ node, const float* __restrict__ euclid,
             const float* __restrict__ W1, const float* __restrict__ b2,
             const float* __restrict__ W3, const float* __restrict__ b3) {
    extern __shared__ char smc[];
    __half* smA  = (__half*)(smc + OFF_A);
    float* P_s   = (float*)(smc + OFF_P);
    float* w1e_s = (float*)(smc + OFF_W1E);
    float* b2_s  = (float*)(smc + OFF_B2V);
    float* w3_s  = (float*)(smc + OFF_W3);
    float* ni_s  = (float*)(smc + OFF_NI);
    float* d_s   = (float*)(smc + OFF_D);
    float* red_s = (float*)(smc + OFF_RED);
    const uint32_t sb = smem_u32(smc);

    const int tid = threadIdx.x, L = tid & 31, wid = tid >> 5;
    const int mw = wid >> 2, nw = wid & 3;           // 2 x 4 warp grid, tile 64x64
    const int m0 = mw * 64, n0 = nw * 64;
    const int b = blockIdx.z, i = blockIdx.y, j0 = blockIdx.x << 7;

    // prefetch L1 chunk 0 -> buf0 (overlaps A staging)
    {
        const __half* src = g_B1h;
#pragma unroll
        for (int r = 0; r < 4; r++) {
            int seg = tid + r * 256, n = seg >> 2, s = seg & 3;
            CP16(sb + OFF_B + n * STRB_B + s * 16, src + n * 32 + s * 8);
        }
        CPCOMMIT();
    }

    // stage small vectors
    P_s[tid]   = g_P[(b * NN + i) * NH + tid];
    w1e_s[tid] = W1[384 * NH + tid];
    b2_s[tid]  = b2[tid];
    w3_s[tid]  = W3[tid];
    if (tid < NE) ni_s[tid] = node[(size_t)(b * NN + i) * NE + tid];
    if (tid < 128) d_s[tid] = euclid[(size_t)(b * NN + i) * NN + j0 + tid];
    __syncthreads();

    // ---- stage A (L1): rows = 128 j-pairs, cols = habs(128), no padding ----
    {
        int row = tid >> 1, half = tid & 1;
        const float4* nj = (const float4*)(node + (size_t)(b * NN + j0 + row) * NE);
        __half* dst = (__half*)((char*)smA + row * STRA_B) + half * 64;
        const float* nip = ni_s + half * 64;
#pragma unroll 8
        for (int q = 0; q < 16; q++) {
            float4 v = nj[half * 16 + q];
            __half2 h0 = __floats2half2_rn(fabsf(nip[q * 4 + 0] - v.x),
                                           fabsf(nip[q * 4 + 1] - v.y));
            __half2 h1v = __floats2half2_rn(fabsf(nip[q * 4 + 2] - v.z),
                                            fabsf(nip[q * 4 + 3] - v.w));
            *(__half2*)(dst + q * 4)     = h0;
            *(__half2*)(dst + q * 4 + 2) = h1v;
        }
    }

    float acc[4][8][4];
#pragma unroll
    for (int mt = 0; mt < 4; mt++)
#pragma unroll
        for (int nt = 0; nt < 8; nt++)
#pragma unroll
            for (int r = 0; r < 4; r++) acc[mt][nt][r] = 0.f;

    // per-thread ldmatrix bases
    const uint32_t rowA = (L & 7) + ((L >> 3) & 1) * 8;
    const uint32_t colA = (L >> 4) * 16;
    const uint32_t aBase = sb + OFF_A + (m0 + rowA) * STRA_B + colA;
    const uint32_t bOff = (n0 + (L & 7)) * STRB_B + ((L >> 3) & 1) * 16;

    // ---- one GEMM layer over uniform 32-k chunks, double-buffered B ----
    auto run_layer = [&](const __half* gB, int nch, const __half* nextB, int phase) {
        for (int c = 0; c < nch; c++) {
            const __half* pre = (c + 1 < nch) ? (gB + (c + 1) * 8192) : nextB;
            if (pre) {
                uint32_t dst = sb + OFF_B + (((c + 1 + phase) & 1) ? BCHUNK_B : 0);
#pragma unroll
                for (int r = 0; r < 4; r++) {
                    int seg = tid + r * 256, n = seg >> 2, s = seg & 3;
                    CP16(dst + n * STRB_B + s * 16, pre + n * 32 + s * 8);
                }
            }
            CPCOMMIT();
            CPWAIT1();
            __syncthreads();
            uint32_t bBase = sb + OFF_B + (((c + phase) & 1) ? BCHUNK_B : 0) + bOff;
            mma_chunk2(acc, aBase + c * 64, bBase);
            __syncthreads();   // WAR fence before this buffer is rewritten
        }
    };

    run_layer(g_B1h, 4, g_B2h, 0);   // last iter prefetches L2 chunk0

    // ---- epilogue 1: h1 = relu(acc + P[i] + Q[j] + d*w1e) -> fp16 A tile ----
#pragma unroll
    for (int mt = 0; mt < 4; mt++) {
        int r0 = m0 + mt * 16 + (L >> 2);
        const float* qA = g_Q + ((size_t)(b * NN + j0 + r0)) * NH;
        const float* qB = qA + 8 * NH;
        float d0 = d_s[r0], d1 = d_s[r0 + 8];
#pragma unroll
        for (int nt = 0; nt < 8; nt++) {
            int cb = n0 + nt * 8 + (L & 3) * 2;
            float p0 = P_s[cb], p1 = P_s[cb + 1];
            float e0 = w1e_s[cb], e1 = w1e_s[cb + 1];
            float2 qa = *(const float2*)(qA + cb);
            float2 qb = *(const float2*)(qB + cb);
            __half2 v0 = __floats2half2_rn(
                fmaxf(fmaf(d0, e0, acc[mt][nt][0] + p0 + qa.x), 0.f),
                fmaxf(fmaf(d0, e1, acc[mt][nt][1] + p1 + qa.y), 0.f));
            __half2 v1 = __floats2half2_rn(
                fmaxf(fmaf(d1, e0, acc[mt][nt][2] + p0 + qb.x), 0.f),
                fmaxf(fmaf(d1, e1, acc[mt][nt][3] + p1 + qb.y), 0.f));
            *(__half2*)((char*)smA + r0 * STRA_B + cb * 2) = v0;
            *(__half2*)((char*)smA + (r0 + 8) * STRA_B + cb * 2) = v1;
            acc[mt][nt][0] = 0.f; acc[mt][nt][1] = 0.f;
            acc[mt][nt][2] = 0.f; acc[mt][nt][3] = 0.f;
        }
    }
    __syncthreads();

    run_layer(g_B2h, 8, nullptr, 4);

    // ---- epilogue 2: out = relu(acc + b2) . W3 ----
    float w3c[16], b2c[16];
#pragma unroll
    for (int nt = 0; nt < 8; nt++) {
        int cb = n0 + nt * 8 + (L & 3) * 2;
        w3c[nt * 2] = w3_s[cb];
        w3c[nt * 2 + 1] = w3_s[cb + 1];
        b2c[nt * 2] = b2_s[cb];
        b2c[nt * 2 + 1] = b2_s[cb + 1];
    }
    float rs[8];
#pragma unroll
    for (int mt = 0; mt < 4; mt++) {
        float s0 = 0.f, s1 = 0.f;
#pragma unroll
        for (int nt = 0; nt < 8; nt++) {
            s0 = fmaf(fmaxf(acc[mt][nt][0] + b2c[nt * 2], 0.f), w3c[nt * 2], s0);
            s0 = fmaf(fmaxf(acc[mt][nt][1] + b2c[nt * 2 + 1], 0.f), w3c[nt * 2 + 1], s0);
            s1 = fmaf(fmaxf(acc[mt][nt][2] + b2c[nt * 2], 0.f), w3c[nt * 2], s1);
            s1 = fmaf(fmaxf(acc[mt][nt][3] + b2c[nt * 2 + 1], 0.f), w3c[nt * 2 + 1], s1);
        }
        rs[mt * 2] = s0;
        rs[mt * 2 + 1] = s1;
    }
#pragma unroll
    for (int r = 0; r < 8; r++) {
        float v = rs[r];
        v += __shfl_xor_sync(0xffffffffu, v, 1);
        v += __shfl_xor_sync(0xffffffffu, v, 2);
        if ((L & 3) == 0) {
            int m = m0 + (r >> 1) * 16 + (r & 1) * 8 + (L >> 2);
            red_s[m * 4 + nw] = v;
        }
    }
    __syncthreads();
    if (tid < 128) {
        float o = red_s[tid * 4] + red_s[tid * 4 + 1] +
                  red_s[tid * 4 + 2] + red_s[tid * 4 + 3] + b3[0];
        g_raw[(size_t)(b * NN + i) * NN + j0 + tid] = o;
    }
}

// ---------------- symmetrize + zero diagonal ----------------
__global__ void symmetrize(float* __restrict__ out) {
    int idx = blockIdx.x * 256 + threadIdx.x;
    int b = idx >> 18;
    int r = idx & 262143;
    int i = r >> 9;
    int j = r & 511;
    float v = 0.f;
    if (i != j)
        v = 0.5f * (g_raw[idx] + g_raw[(b << 18) + (j << 9) + i]);
    out[idx] = v;
}

extern "C" void kernel_launch(void* const* d_in, const int* in_sizes, int n_in,
                              void* d_out, int out_size) {
    const float* node   = (const float*)d_in[0];
    const float* euclid = (const float*)d_in[2];
    const float* W1 = (const float*)d_in[3];
    const float* b1 = (const float*)d_in[4];
    const float* W2 = (const float*)d_in[5];
    const float* b2 = (const float*)d_in[6];
    const float* W3 = (const float*)d_in[7];
    const float* b3 = (const float*)d_in[8];
    float* out = (float*)d_out;

    cudaFuncSetAttribute(edge_mlp_mma, cudaFuncAttributeMaxDynamicSharedMemorySize,
                         SMEM_REQ);

    prep_all<<<1024 + 384, 256>>>(node, W1, b1, W2);
    dim3 grid(NN / 128, NN, NB);
    edge_mlp_mma<<<grid, 256, SMEM_REQ>>>(node, euclid, W1, b2, W3, b3);
    symmetrize<<<(NB * NN * NN) / 256, 256>>>(out);
}